// round 9
// baseline (speedup 1.0000x reference)
#include <cuda_runtime.h>

#define NS   1024
#define XD   128
#define HID  256
#define NBLK 256

typedef unsigned long long u64;
union F2 { u64 u; float f[2]; };

// Scratch (device globals — no allocation allowed)
__device__ float g_px_t[HID * NS];   // pre_x transposed: [k][j]
__device__ u64   g_pyd[HID * NS];    // (pre_y + b1) transposed, duplicated (v,v): [k][i]
__device__ u64   g_w2p[HID];         // W2 packed (w,w)
__device__ float g_sum_exp;
__device__ float g_sum_diag;
__device__ unsigned g_phase;         // phase-A arrival counter
__device__ unsigned g_done;          // phase-B completion counter

__device__ __forceinline__ u64 pack2(float lo, float hi) {
    u64 r; asm("mov.b64 %0, {%1, %2};" : "=l"(r) : "f"(lo), "f"(hi)); return r;
}
__device__ __forceinline__ u64 add2(u64 a, u64 b) {
    u64 r; asm("add.rn.f32x2 %0, %1, %2;" : "=l"(r) : "l"(a), "l"(b)); return r;
}
__device__ __forceinline__ u64 fma2(u64 a, u64 b, u64 c) {
    u64 r; asm("fma.rn.f32x2 %0, %1, %2, %3;" : "=l"(r) : "l"(a), "l"(b), "l"(c)); return r;
}
__device__ __forceinline__ u64 relu2(u64 a) {
    F2 v; v.u = a;
    v.f[0] = fmaxf(v.f[0], 0.0f);
    v.f[1] = fmaxf(v.f[1], 0.0f);
    return v.u;
}
__device__ __forceinline__ void cpa16(void* smem, const void* gmem) {
    unsigned s = (unsigned)__cvta_generic_to_shared(smem);
    asm volatile("cp.async.cg.shared.global [%0], [%1], 16;" :: "r"(s), "l"(gmem));
}
__device__ __forceinline__ void cpa_commit() {
    asm volatile("cp.async.commit_group;");
}
template <int N>
__device__ __forceinline__ void cpa_wait() {
    asm volatile("cp.async.wait_group %0;" :: "n"(N));
}
__device__ __forceinline__ unsigned ld_acq(const unsigned* p) {
    unsigned v;
    asm volatile("ld.global.acquire.gpu.u32 %0, [%1];" : "=r"(v) : "l"(p));
    return v;
}

// Shared memory union: phase A (GEMM tiles) overlaps phase B (pairwise tiles).
union SmemU {
    struct {                     // phase A: 24 KB
        float As[64][32];        // [k][n]   8 KB
        float Ws[64][64];        // [k][h]  16 KB
    } a;
    struct {                     // phase B: 26 KB
        u64   Ys[2][16][64];     // [buf][k][i]  (v,v)  16 KB
        float Xs[2][16][64];     // [buf][k][j]          8 KB
        u64   w2[HID];           //                      2 KB
    } b;
};

// ---------------------------------------------------------------------------
// ONE fused kernel. grid (16,16) = 256 blocks, 128 threads.
// Phase A: pre-GEMM slice per block (32n x 64h of one of the two matrices).
// Spin barrier (all 256 blocks guaranteed co-resident: 128thr/27KB smem).
// Phase B: pairwise 64i x 64j tile, micro 4i x 8j = 32 products/thread.
// ---------------------------------------------------------------------------
__global__ void __launch_bounds__(128)
fused_kernel(const float* __restrict__ x,
             const float* __restrict__ y,
             const float* __restrict__ W1,
             const float* __restrict__ b1,
             const float* __restrict__ W2,
             const float* __restrict__ b2,
             float* __restrict__ out) {
    __shared__ SmemU sm;
    __shared__ float r1[4], r2[4];
    __shared__ bool  is_last;

    const int t   = threadIdx.x;                 // 0..127
    const int bid = blockIdx.y * 16 + blockIdx.x;

    // ===================== Phase A: pre-GEMM =====================
    {
        const int m  = bid >> 7;                 // matrix: 0 = x, 1 = y
        const int r  = bid & 127;
        const int n0 = (r >> 2) * 32;
        const int h0 = (r & 3) * 64;
        const float* __restrict__ A = m ? y : x;
        const float* __restrict__ W = W1 + (m ? (XD * HID) : 0);

        if (bid == 0) {
            if (t == 0) { g_sum_exp = 0.0f; g_sum_diag = 0.0f; }
            float wa = W2[t];       g_w2p[t]       = pack2(wa, wa);
            float wb = W2[t + 128]; g_w2p[t + 128] = pack2(wb, wb);
        }

        const int tn = t >> 4;     // 0..7   n-local = tn*4
        const int th = t & 15;     // 0..15  h-local = th*4

        float accf[4][4];
#pragma unroll
        for (int a = 0; a < 4; a++)
#pragma unroll
            for (int b = 0; b < 4; b++) accf[a][b] = 0.0f;

        for (int kc = 0; kc < XD; kc += 64) {
            // As[k][n]: 32 rows x 64 k, transposed on store. 4 float4/thread.
#pragma unroll
            for (int q = 0; q < 4; q++) {
                int f   = t + q * 128;
                int row = f >> 4;            // 0..31
                int c4  = (f & 15) * 4;      // 0..60
                float4 v = *(const float4*)&A[(n0 + row) * XD + kc + c4];
                sm.a.As[c4 + 0][row] = v.x;
                sm.a.As[c4 + 1][row] = v.y;
                sm.a.As[c4 + 2][row] = v.z;
                sm.a.As[c4 + 3][row] = v.w;
            }
            // Ws[k][h]: 64 k x 64 h. 8 float4/thread, no transpose.
#pragma unroll
            for (int q = 0; q < 8; q++) {
                int f  = t + q * 128;
                int k  = f >> 4;             // 0..63
                int c4 = (f & 15) * 4;
                *(float4*)&sm.a.Ws[k][c4] =
                    *(const float4*)&W[(kc + k) * HID + h0 + c4];
            }
            __syncthreads();

#pragma unroll 8
            for (int k = 0; k < 64; k++) {
                float4 a4 = *(const float4*)&sm.a.As[k][tn * 4];
                float4 w4 = *(const float4*)&sm.a.Ws[k][th * 4];
                float aa[4] = {a4.x, a4.y, a4.z, a4.w};
                float ww[4] = {w4.x, w4.y, w4.z, w4.w};
#pragma unroll
                for (int a = 0; a < 4; a++)
#pragma unroll
                    for (int b = 0; b < 4; b++)
                        accf[a][b] = fmaf(aa[a], ww[b], accf[a][b]);
            }
            __syncthreads();
        }

        if (m == 0) {
#pragma unroll
            for (int b = 0; b < 4; b++) {
                int h = h0 + th * 4 + b;
                float4 v = make_float4(accf[0][b], accf[1][b], accf[2][b], accf[3][b]);
                *(float4*)&g_px_t[h * NS + n0 + tn * 4] = v;
            }
        } else {
#pragma unroll
            for (int b = 0; b < 4; b++) {
                int h = h0 + th * 4 + b;
                float bias = b1[h];
                u64 v0 = pack2(accf[0][b] + bias, accf[0][b] + bias);
                u64 v1 = pack2(accf[1][b] + bias, accf[1][b] + bias);
                u64 v2 = pack2(accf[2][b] + bias, accf[2][b] + bias);
                u64 v3 = pack2(accf[3][b] + bias, accf[3][b] + bias);
                ulonglong2* dst = (ulonglong2*)&g_pyd[h * NS + n0 + tn * 4];
                dst[0] = make_ulonglong2(v0, v1);
                dst[1] = make_ulonglong2(v2, v3);
            }
        }
    }

    // ===================== Device-wide barrier =====================
    __threadfence();
    __syncthreads();
    if (t == 0) {
        atomicAdd(&g_phase, 1u);
        while (ld_acq(&g_phase) < NBLK) {
            __nanosleep(40);
        }
    }
    __syncthreads();

    // ===================== Phase B: pairwise =====================
    const int gi = t & 15;          // i = gi*4
    const int gj = t >> 4;          // j = gj*8
    const int bi = blockIdx.y * 64;
    const int bj = blockIdx.x * 64;

    sm.b.w2[t]       = g_w2p[t];
    sm.b.w2[t + 128] = g_w2p[t + 128];

    auto load_stage = [&](int buf, int kk) {
        // Ys: 16k x 64i u64 = 512 x 16B; 4 per thread.
#pragma unroll
        for (int q = 0; q < 4; q++) {
            int f  = t + q * 128;
            int k  = f >> 5;                 // 0..15
            int c2 = (f & 31) * 2;
            cpa16(&sm.b.Ys[buf][k][c2], &g_pyd[(kk + k) * NS + bi + c2]);
        }
        // Xs: 16k x 64j float = 256 x 16B; 2 per thread.
#pragma unroll
        for (int q = 0; q < 2; q++) {
            int f  = t + q * 128;
            int k  = f >> 4;                 // 0..15
            int c4 = (f & 15) * 4;
            cpa16(&sm.b.Xs[buf][k][c4], &g_px_t[(kk + k) * NS + bj + c4]);
        }
        cpa_commit();
    };

    u64 acc[4][4];
#pragma unroll
    for (int a = 0; a < 4; a++)
#pragma unroll
        for (int p = 0; p < 4; p++) acc[a][p] = 0ull;

    load_stage(0, 0);

    const int NCHUNK = HID / 16;    // 16
    for (int it = 0; it < NCHUNK; it++) {
        const int cur = it & 1;
        if (it + 1 < NCHUNK) {
            load_stage(cur ^ 1, (it + 1) * 16);
            cpa_wait<1>();
        } else {
            cpa_wait<0>();
        }
        __syncthreads();

        const int kk = it * 16;
#pragma unroll 8
        for (int k = 0; k < 16; k++) {
            ulonglong2 ya = *(const ulonglong2*)&sm.b.Ys[cur][k][gi * 4];
            ulonglong2 yb = *(const ulonglong2*)&sm.b.Ys[cur][k][gi * 4 + 2];
            ulonglong2 xa = *(const ulonglong2*)&sm.b.Xs[cur][k][gj * 8];
            ulonglong2 xb = *(const ulonglong2*)&sm.b.Xs[cur][k][gj * 8 + 4];
            u64 w = sm.b.w2[kk + k];
            u64 yp[4] = {ya.x, ya.y, yb.x, yb.y};
            u64 xp[4] = {xa.x, xa.y, xb.x, xb.y};
#pragma unroll
            for (int a = 0; a < 4; a++)
#pragma unroll
                for (int p = 0; p < 4; p++) {
                    u64 s = relu2(add2(yp[a], xp[p]));
                    acc[a][p] = fma2(s, w, acc[a][p]);
                }
        }
        __syncthreads();
    }

    // ===================== Epilogue =====================
    const float c = b2[0] - 1.0f;
    float sexp = 0.0f, sdiag = 0.0f;

#pragma unroll
    for (int a = 0; a < 4; a++)
#pragma unroll
        for (int p = 0; p < 4; p++) {
            F2 v; v.u = acc[a][p];
            sexp += __expf(v.f[0] + c) + __expf(v.f[1] + c);
        }

    // Diagonal: global i == global j.  i = bi + gi*4 + a, j-range = bj + gj*8 .. +7.
#pragma unroll
    for (int a = 0; a < 4; a++) {
        int jj = bi + gi * 4 + a - bj;
        if (jj >= 0 && jj < 64 && (jj >> 3) == gj) {
            int off = jj & 7;
            F2 v; v.u = acc[a][off >> 1];
            sdiag += v.f[off & 1] + c;
        }
    }

    const int lane = t & 31, wid = t >> 5;
#pragma unroll
    for (int o = 16; o > 0; o >>= 1) {
        sexp  += __shfl_down_sync(0xFFFFFFFFu, sexp,  o);
        sdiag += __shfl_down_sync(0xFFFFFFFFu, sdiag, o);
    }
    if (lane == 0) { r1[wid] = sexp; r2[wid] = sdiag; }
    __syncthreads();
    if (t == 0) {
        float s1 = r1[0] + r1[1] + r1[2] + r1[3];
        float s2 = r2[0] + r2[1] + r2[2] + r2[3];
        atomicAdd(&g_sum_exp,  s1);
        atomicAdd(&g_sum_diag, s2);
        __threadfence();
        unsigned v = atomicAdd(&g_done, 1u);
        is_last = (v == NBLK - 1);
    }
    __syncthreads();

    if (is_last && t == 0) {
        // Reset counters for next graph replay; then finalize.
        g_done  = 0;
        g_phase = 0;
        float n = (float)NS;
        float se = __ldcg(&g_sum_exp);
        float sd = __ldcg(&g_sum_diag);
        out[0] = (sd + n) / n - se / (n * n);
    }
}

// ---------------------------------------------------------------------------
extern "C" void kernel_launch(void* const* d_in, const int* in_sizes, int n_in,
                              void* d_out, int out_size) {
    const float* x  = (const float*)d_in[0];
    const float* y  = (const float*)d_in[1];
    const float* W1 = (const float*)d_in[2];
    const float* b1 = (const float*)d_in[3];
    const float* W2 = (const float*)d_in[4];
    const float* b2 = (const float*)d_in[5];
    float* out = (float*)d_out;

    dim3 grid(16, 16);
    fused_kernel<<<grid, 128>>>(x, y, W1, b1, W2, b2, out);
}